// round 7
// baseline (speedup 1.0000x reference)
#include <cuda_runtime.h>
#include <cuda_bf16.h>
#include <cstdint>

#define NN 50000
#define NP 50048
#define NE 600000
#define NG 64
#define HID 128
#define NL 4
#define INDIM 5
#define NCLS 5
#define WSTRIDE 136                  // bf16 row stride (272B = 4-bank shift/row)

// ---------------- device scratch ----------------
__device__ int   d_deg[NN];
__device__ int   d_rowptr[NN + 1];
__device__ int   d_cursor[NN];
__device__ int2  d_colw[NE];
__device__ float d_dinv[NN];
__device__ float d_bufM[(size_t)NP * HID];
__device__ float d_bufA[(size_t)NP * HID];
__device__ float d_sums[2][256];
__device__ int   d_gstart[NG + 1];
__device__ __align__(16) __nv_bfloat16 d_wh[NL][HID * WSTRIDE];   // W^T hi image
__device__ __align__(16) __nv_bfloat16 d_wl[NL][HID * WSTRIDE];   // W^T lo image

// ---------------- mma.sync bf16 (sm_80 core ISA) ----------------
#define MMA16816(c, a0, a1, a2, a3, b0, b1) \
    asm volatile("mma.sync.aligned.m16n8k16.row.col.f32.bf16.bf16.f32 " \
        "{%0,%1,%2,%3}, {%4,%5,%6,%7}, {%8,%9}, {%0,%1,%2,%3};" \
        : "+f"((c)[0]), "+f"((c)[1]), "+f"((c)[2]), "+f"((c)[3]) \
        : "r"(a0), "r"(a1), "r"(a2), "r"(a3), "r"(b0), "r"(b1))

__device__ __forceinline__ uint32_t packbf2(float a, float b) {
    __nv_bfloat162 h = __floats2bfloat162_rn(a, b);
    return *reinterpret_cast<uint32_t*>(&h);
}

// ---------------- wprep: W^T hi/lo images + gbounds + zero deg + zero sums ----------------
__global__ void wprep_k(const float* __restrict__ Wg, const int* __restrict__ batch) {
    int b = blockIdx.x, tid = threadIdx.x;
    if (b < NL) {
        const float* W = Wg + (size_t)b * HID * HID;
        for (int i = tid; i < HID * HID; i += 256) {
            int n = i >> 7, k = i & 127;
            float w = W[k * HID + n];                   // B^T[n][k] = W[k][n]
            __nv_bfloat16 wh = __float2bfloat16(w);
            float res = w - __bfloat162float(wh);
            d_wh[b][n * WSTRIDE + k] = wh;
            d_wl[b][n * WSTRIDE + k] = __float2bfloat16(res);
        }
    } else if (b == NL) {
        if (tid <= NG) {
            int g = tid, lo = 0, hi = NN;
            while (lo < hi) { int mid = (lo + hi) >> 1; if (batch[mid] < g) lo = mid + 1; else hi = mid; }
            d_gstart[g] = lo;
        }
        if (tid < 256) { d_sums[0][tid] = 0.f; d_sums[1][tid] = 0.f; }
    } else {
        for (int i = (b - NL - 1) * 256 + tid; i < NN; i += (gridDim.x - NL - 1) * 256) d_deg[i] = 0;
    }
}

// ---------------- CSR build ----------------
__global__ void hist_k(const int* __restrict__ ei) {
    int e = blockIdx.x * blockDim.x + threadIdx.x;
    if (e < NE) atomicAdd(&d_deg[ei[NE + e]], 1);
}

// single-block exclusive scan over d_deg (1024 thr x 49 elems)
__global__ void scan_k() {
    __shared__ int sh[1024];
    const int PER = 49;
    int t = threadIdx.x;
    int base = t * PER;
    int s = 0;
#pragma unroll 7
    for (int i = 0; i < PER; i++) {
        int idx = base + i;
        if (idx < NN) s += d_deg[idx];
    }
    sh[t] = s;
    __syncthreads();
    for (int off = 1; off < 1024; off <<= 1) {
        int v = (t >= off) ? sh[t - off] : 0;
        __syncthreads();
        sh[t] += v;
        __syncthreads();
    }
    int run = sh[t] - s;   // exclusive prefix
    for (int i = 0; i < PER; i++) {
        int idx = base + i;
        if (idx < NN) {
            int dg = d_deg[idx];
            d_rowptr[idx] = run;
            d_cursor[idx] = run;
            d_dinv[idx] = rsqrtf((float)(dg + 1));
            run += dg;
        }
    }
    if (t == 1023) d_rowptr[NN] = NE;
}

__global__ void scatter_k(const int* __restrict__ ei) {
    int e = blockIdx.x * blockDim.x + threadIdx.x;
    if (e >= NE) return;
    int s = ei[e], t = ei[NE + e];
    int p = atomicAdd(&d_cursor[t], 1);
    int2 v;
    v.x = s;
    v.y = __float_as_int(d_dinv[s] * d_dinv[t]);
    d_colw[p] = v;
}

// ---------------- fused GEMM: M = act(A) @ W via mma.sync bf16-split ----------------
// smem (bf16 elems): Wh[128*136] | Wl | Ah | Al ; then 768 floats (sx)
#define GS_WH 0
#define GS_WL (HID * WSTRIDE)
#define GS_AH (2 * HID * WSTRIDE)
#define GS_AL (3 * HID * WSTRIDE)
#define GEMM_SMEM (4 * HID * WSTRIDE * 2 + 768 * 4)

__global__ void __launch_bounds__(256, 1) gemm_k(
    const float* __restrict__ x, const float* __restrict__ Wp, const float* __restrict__ bp,
    const float* __restrict__ gammaP, const float* __restrict__ betaP, int layer)
{
    extern __shared__ __align__(16) __nv_bfloat16 smb[];
    float* sx = reinterpret_cast<float*>(smb + 4 * HID * WSTRIDE);
    int tid = threadIdx.x;
    int row0 = blockIdx.x * 128;

    if (blockIdx.x == 0) d_sums[layer & 1][tid] = 0.f;

    if (layer == 0) {
        for (int i = tid; i < INDIM * HID; i += 256) sx[i] = Wp[i];
        if (tid < HID) sx[INDIM * HID + tid] = bp[tid];
    } else if (tid < HID) {
        int par = (layer - 1) & 1;
        float mu = d_sums[par][tid] * (1.0f / NN);
        float var = d_sums[par][128 + tid] * (1.0f / NN) - mu * mu;
        float a = gammaP[tid] * rsqrtf(var + 1e-5f);
        sx[tid] = a;
        sx[128 + tid] = betaP[tid] - mu * a;
    }

    // copy W images (linear uint4)
    {
        const uint4* sh = reinterpret_cast<const uint4*>(d_wh[layer]);
        const uint4* sl = reinterpret_cast<const uint4*>(d_wl[layer]);
        uint4* dh = reinterpret_cast<uint4*>(smb + GS_WH);
        uint4* dl = reinterpret_cast<uint4*>(smb + GS_WL);
        for (int i = tid; i < HID * WSTRIDE / 8; i += 256) { dh[i] = sh[i]; dl[i] = sl[i]; }
    }
    __syncthreads();

    // A tile build: (proj | BN+ReLU) then split hi/lo bf16
    for (int i = tid; i < 128 * 32; i += 256) {
        int r = i >> 5, c = (i & 31) << 2;
        float4 v;
        if (layer == 0) {
            int gr = row0 + r;
            float xr[INDIM];
#pragma unroll
            for (int j = 0; j < INDIM; j++) xr[j] = (gr < NN) ? __ldg(&x[gr * INDIM + j]) : 0.f;
            float o[4];
#pragma unroll
            for (int cc = 0; cc < 4; cc++) {
                float s = sx[INDIM * HID + c + cc];
#pragma unroll
                for (int j = 0; j < INDIM; j++) s = fmaf(xr[j], sx[j * HID + c + cc], s);
                o[cc] = s;
            }
            v = make_float4(o[0], o[1], o[2], o[3]);
        } else {
            v = *reinterpret_cast<const float4*>(d_bufA + (size_t)(row0 + r) * HID + c);
            v.x = fmaxf(fmaf(sx[c    ], v.x, sx[128 + c    ]), 0.f);
            v.y = fmaxf(fmaf(sx[c + 1], v.y, sx[128 + c + 1]), 0.f);
            v.z = fmaxf(fmaf(sx[c + 2], v.z, sx[128 + c + 2]), 0.f);
            v.w = fmaxf(fmaf(sx[c + 3], v.w, sx[128 + c + 3]), 0.f);
        }
        __nv_bfloat16 hx = __float2bfloat16(v.x), hy = __float2bfloat16(v.y);
        __nv_bfloat16 hz = __float2bfloat16(v.z), hw = __float2bfloat16(v.w);
        uint32_t base = r * WSTRIDE + c;
        *reinterpret_cast<uint2*>(smb + GS_AH + base) = make_uint2(
            packbf2(__bfloat162float(hx), __bfloat162float(hy)),
            packbf2(__bfloat162float(hz), __bfloat162float(hw)));
        *reinterpret_cast<uint2*>(smb + GS_AL + base) = make_uint2(
            packbf2(v.x - __bfloat162float(hx), v.y - __bfloat162float(hy)),
            packbf2(v.z - __bfloat162float(hz), v.w - __bfloat162float(hw)));
    }
    __syncthreads();

    // compute: warp w -> rows w*16..w*16+15, all 128 cols
    int w = tid >> 5, lane = tid & 31;
    int gid = lane >> 2, q = lane & 3;
    const __nv_bfloat16* Ah = smb + GS_AH + (w * 16) * WSTRIDE;
    const __nv_bfloat16* Al = smb + GS_AL + (w * 16) * WSTRIDE;
    const __nv_bfloat16* Wh = smb + GS_WH;
    const __nv_bfloat16* Wl = smb + GS_WL;

    float acc[16][4];
#pragma unroll
    for (int j = 0; j < 16; j++)
#pragma unroll
        for (int r = 0; r < 4; r++) acc[j][r] = 0.f;

#pragma unroll
    for (int ks = 0; ks < 8; ks++) {
        int k0 = ks * 16 + q * 2;
        uint32_t a0h = *reinterpret_cast<const uint32_t*>(Ah + gid * WSTRIDE + k0);
        uint32_t a1h = *reinterpret_cast<const uint32_t*>(Ah + (gid + 8) * WSTRIDE + k0);
        uint32_t a2h = *reinterpret_cast<const uint32_t*>(Ah + gid * WSTRIDE + k0 + 8);
        uint32_t a3h = *reinterpret_cast<const uint32_t*>(Ah + (gid + 8) * WSTRIDE + k0 + 8);
        uint32_t a0l = *reinterpret_cast<const uint32_t*>(Al + gid * WSTRIDE + k0);
        uint32_t a1l = *reinterpret_cast<const uint32_t*>(Al + (gid + 8) * WSTRIDE + k0);
        uint32_t a2l = *reinterpret_cast<const uint32_t*>(Al + gid * WSTRIDE + k0 + 8);
        uint32_t a3l = *reinterpret_cast<const uint32_t*>(Al + (gid + 8) * WSTRIDE + k0 + 8);
#pragma unroll
        for (int j = 0; j < 16; j++) {
            uint32_t nb = (j * 8 + gid) * WSTRIDE + k0;
            uint32_t b0h = *reinterpret_cast<const uint32_t*>(Wh + nb);
            uint32_t b1h = *reinterpret_cast<const uint32_t*>(Wh + nb + 8);
            uint32_t b0l = *reinterpret_cast<const uint32_t*>(Wl + nb);
            uint32_t b1l = *reinterpret_cast<const uint32_t*>(Wl + nb + 8);
            MMA16816(acc[j], a0h, a1h, a2h, a3h, b0h, b1h);
            MMA16816(acc[j], a0h, a1h, a2h, a3h, b0l, b1l);
            MMA16816(acc[j], a0l, a1l, a2l, a3l, b0h, b1h);
        }
    }

    // epilogue
    size_t r1 = row0 + w * 16 + gid;
    size_t r2 = r1 + 8;
#pragma unroll
    for (int j = 0; j < 16; j++) {
        int cc = j * 8 + q * 2;
        *reinterpret_cast<float2*>(d_bufM + r1 * HID + cc) = make_float2(acc[j][0], acc[j][1]);
        *reinterpret_cast<float2*>(d_bufM + r2 * HID + cc) = make_float2(acc[j][2], acc[j][3]);
    }
}

// ---------------- aggregation + fused BN stats ----------------
__global__ void __launch_bounds__(256) agg_k(const float* __restrict__ bg, int par) {
    __shared__ float shs[128], shq[128];
    int tid = threadIdx.x;
    int lane = tid & 31;
    if (tid < 128) { shs[tid] = 0.f; shq[tid] = 0.f; }
    __syncthreads();

    float4 s4 = make_float4(0.f, 0.f, 0.f, 0.f);
    float4 q4 = make_float4(0.f, 0.f, 0.f, 0.f);
    float4 b = *reinterpret_cast<const float4*>(bg + lane * 4);

    int w0 = blockIdx.x * 8 + (tid >> 5);
    int stride = gridDim.x * 8;
    for (int n = w0; n < NN; n += stride) {
        int st = d_rowptr[n], en = d_rowptr[n + 1];
        float4 acc = make_float4(0.f, 0.f, 0.f, 0.f);
        for (int e = st; e < en; e++) {
            int2 cw = __ldg(&d_colw[e]);
            float wt = __int_as_float(cw.y);
            float4 mv = *reinterpret_cast<const float4*>(d_bufM + (size_t)cw.x * HID + lane * 4);
            acc.x = fmaf(wt, mv.x, acc.x);
            acc.y = fmaf(wt, mv.y, acc.y);
            acc.z = fmaf(wt, mv.z, acc.z);
            acc.w = fmaf(wt, mv.w, acc.w);
        }
        float di = d_dinv[n];
        float ws = di * di;
        float4 mv = *reinterpret_cast<const float4*>(d_bufM + (size_t)n * HID + lane * 4);
        acc.x = fmaf(ws, mv.x, acc.x) + b.x;
        acc.y = fmaf(ws, mv.y, acc.y) + b.y;
        acc.z = fmaf(ws, mv.z, acc.z) + b.z;
        acc.w = fmaf(ws, mv.w, acc.w) + b.w;
        *reinterpret_cast<float4*>(d_bufA + (size_t)n * HID + lane * 4) = acc;
        s4.x += acc.x; s4.y += acc.y; s4.z += acc.z; s4.w += acc.w;
        q4.x = fmaf(acc.x, acc.x, q4.x); q4.y = fmaf(acc.y, acc.y, q4.y);
        q4.z = fmaf(acc.z, acc.z, q4.z); q4.w = fmaf(acc.w, acc.w, q4.w);
    }

    int ch = lane * 4;
    atomicAdd(&shs[ch    ], s4.x); atomicAdd(&shs[ch + 1], s4.y);
    atomicAdd(&shs[ch + 2], s4.z); atomicAdd(&shs[ch + 3], s4.w);
    atomicAdd(&shq[ch    ], q4.x); atomicAdd(&shq[ch + 1], q4.y);
    atomicAdd(&shq[ch + 2], q4.z); atomicAdd(&shq[ch + 3], q4.w);
    __syncthreads();
    if (tid < 128) {
        atomicAdd(&d_sums[par][tid], shs[tid]);
        atomicAdd(&d_sums[par][128 + tid], shq[tid]);
    }
}

// ---------------- pool + MLP head ----------------
__global__ void __launch_bounds__(256) poolhead_k(
    const float* __restrict__ gamma3, const float* __restrict__ beta3,
    const float* __restrict__ W1, const float* __restrict__ b1,
    const float* __restrict__ W2, const float* __restrict__ b2,
    const float* __restrict__ W3, const float* __restrict__ b3,
    float* __restrict__ out)
{
    __shared__ float sbn[256], shs[256], shm[256], pooled[256], h1[128], h2[64];
    int g = blockIdx.x, tid = threadIdx.x;
    if (tid < 128) {
        float mu = d_sums[1][tid] * (1.0f / NN);
        float var = d_sums[1][128 + tid] * (1.0f / NN) - mu * mu;
        float a = gamma3[tid] * rsqrtf(var + 1e-5f);
        sbn[tid] = a;
        sbn[128 + tid] = beta3[tid] - mu * a;
    }
    __syncthreads();
    int st = d_gstart[g], en = d_gstart[g + 1];
    int ch = tid & 127, half = tid >> 7;
    float a = sbn[ch], bb = sbn[128 + ch];
    float s = 0.f, mx = 0.f;
    for (int r = st + half; r < en; r += 2) {
        float v = fmaxf(fmaf(a, d_bufA[(size_t)r * HID + ch], bb), 0.f);
        s += v;
        mx = fmaxf(mx, v);
    }
    shs[tid] = s;
    shm[tid] = mx;
    __syncthreads();
    if (tid < 128) {
        float cnt = (float)(en - st);
        pooled[tid] = (shs[tid] + shs[tid + 128]) / fmaxf(cnt, 1.0f);
        pooled[128 + tid] = fmaxf(shm[tid], shm[tid + 128]);
    }
    __syncthreads();
    if (tid < 128) {
        float acc = b1[tid];
#pragma unroll 8
        for (int k = 0; k < 256; k++) acc = fmaf(pooled[k], W1[k * HID + tid], acc);
        h1[tid] = fmaxf(acc, 0.f);
    }
    __syncthreads();
    if (tid < 64) {
        float acc = b2[tid];
#pragma unroll 8
        for (int k = 0; k < 128; k++) acc = fmaf(h1[k], W2[k * 64 + tid], acc);
        h2[tid] = fmaxf(acc, 0.f);
    }
    __syncthreads();
    if (tid < NCLS) {
        float acc = b3[tid];
#pragma unroll 8
        for (int k = 0; k < 64; k++) acc = fmaf(h2[k], W3[k * NCLS + tid], acc);
        out[g * NCLS + tid] = acc;
    }
}

// ---------------- launch ----------------
extern "C" void kernel_launch(void* const* d_in, const int* in_sizes, int n_in,
                              void* d_out, int out_size) {
    const float* x     = (const float*)d_in[0];
    const int*   ei    = (const int*)d_in[1];
    const int*   batch = (const int*)d_in[2];
    const float* Wp    = (const float*)d_in[3];
    const float* bp    = (const float*)d_in[4];
    const float* Wg    = (const float*)d_in[5];
    const float* bg    = (const float*)d_in[6];
    const float* gamma = (const float*)d_in[7];
    const float* beta  = (const float*)d_in[8];
    const float* W1    = (const float*)d_in[9];
    const float* b1    = (const float*)d_in[10];
    const float* W2    = (const float*)d_in[11];
    const float* b2    = (const float*)d_in[12];
    const float* W3    = (const float*)d_in[13];
    const float* b3    = (const float*)d_in[14];
    float* out = (float*)d_out;

    cudaFuncSetAttribute(gemm_k, cudaFuncAttributeMaxDynamicSharedMemorySize, GEMM_SMEM);

    wprep_k<<<64, 256>>>(Wg, batch);
    hist_k<<<(NE + 255) / 256, 256>>>(ei);
    scan_k<<<1, 1024>>>();
    scatter_k<<<(NE + 255) / 256, 256>>>(ei);

    for (int i = 0; i < NL; i++) {
        gemm_k<<<NP / 128, 256, GEMM_SMEM>>>(
            x, Wp, bp,
            i > 0 ? gamma + (i - 1) * HID : gamma,
            i > 0 ? beta + (i - 1) * HID : beta, i);
        agg_k<<<1024, 256>>>(bg + i * HID, i & 1);
    }

    poolhead_k<<<NG, 256>>>(gamma + 3 * HID, beta + 3 * HID, W1, b1, W2, b2, W3, b3, out);
}